// round 5
// baseline (speedup 1.0000x reference)
#include <cuda_runtime.h>

#define NB 32
#define NT 8192
#define NC 1024
#define NH 16
#define SCALE 0.03125f   // 1024^-0.5

#define TILE_R 256
#define KC 16
#define XSTR 20                  // 16 + 4 pad: xv LDS conflict-free
#define NCH (NC / KC)            // 64
#define SC_TILES (NT / TILE_R)   // 32 scores tiles per batch
#define PL_TILES 64              // 128-row pool tiles per batch
#define NTASK 3072

// ---- scratch ----
__device__ float    g_scores[(size_t)NB * NT * NH];
__device__ float    g_Z[NB * NH];
__device__ float    g_pooled[NB * NC];
__device__ unsigned g_ticket;
__device__ unsigned g_done[NB];

__device__ __forceinline__ void ffma2(unsigned long long& d,
                                      unsigned long long a,
                                      unsigned long long b) {
    asm("fma.rn.f32x2 %0, %1, %2, %0;" : "+l"(d) : "l"(a), "l"(b));
}
__device__ __forceinline__ float lo2(unsigned long long a) { return __uint_as_float((unsigned)a); }
__device__ __forceinline__ float hi2(unsigned long long a) { return __uint_as_float((unsigned)(a >> 32)); }

// ============================================================
__global__ void k_zero() {
    int i = blockIdx.x * blockDim.x + threadIdx.x;
    if (i < NB * NC) g_pooled[i] = 0.0f;
    if (i < NB * NH) g_Z[i] = 0.0f;
    if (i < NB)      g_done[i] = 0u;
    if (i == 0)      g_ticket = 0u;
}

// ============================================================
// Persistent task-graph kernel: scores tiles + pool tiles overlapped.
// ============================================================
__global__ void __launch_bounds__(256, 2)
k_main(const float* __restrict__ x, const float* __restrict__ q) {
    extern __shared__ float sm[];
    float* qs = sm;                      // 16*1024 floats (64 KB)
    float* xs = sm + NH * NC;            // 256*20 floats  (20 KB)
    __shared__ float zsh[NH];
    __shared__ float ws[128];
    __shared__ float rz[16];
    __shared__ int   s_task;

    const int tid = threadIdx.x;
    bool qstaged = false;

    for (;;) {
        __syncthreads();                     // smem safe for reuse
        if (tid == 0) s_task = (int)atomicAdd(&g_ticket, 1u);
        __syncthreads();
        const int t = s_task;
        if (t >= NTASK) break;

        int type, grp, local;
        if      (t < 256)  { type = 0; grp = 0; local = t; }
        else if (t < 512)  { type = 0; grp = 1; local = t - 256; }
        else if (t < 1024) { type = 1; grp = 0; local = t - 512; }
        else if (t < 1280) { type = 0; grp = 2; local = t - 1024; }
        else if (t < 1792) { type = 1; grp = 1; local = t - 1280; }
        else if (t < 2048) { type = 0; grp = 3; local = t - 1792; }
        else if (t < 2560) { type = 1; grp = 2; local = t - 2048; }
        else               { type = 1; grp = 3; local = t - 2560; }

        if (type == 0) {
            // ================= SCORES tile: 256 rows x 16 heads =================
            const int b = grp * 8 + local / SC_TILES;
            const int tile = local % SC_TILES;

            if (!qstaged) {
                for (int i = tid; i < NH * NC / 4; i += 256)
                    ((float4*)qs)[i] = ((const float4*)q)[i];
                __syncthreads();
                qstaged = true;
            }
            if (tid < NH) zsh[tid] = 0.0f;

            const int rowg = tid & 127, headg = tid >> 7;    // 128 x 2
            const int crow = tid >> 2, ccol = (tid & 3) * 4; // copy: 4 lanes/row
            const float* xb = x + ((size_t)(b * NT + tile * TILE_R)) * NC;

            float4 r[4];
#define LOADC(c)                                                            \
            _Pragma("unroll")                                               \
            for (int g = 0; g < 4; g++)                                     \
                r[g] = *(const float4*)(xb + (size_t)(g * 64 + crow) * NC   \
                                        + (c) * KC + ccol);
            LOADC(0);

            unsigned long long acc[2][8];
            #pragma unroll
            for (int m = 0; m < 2; m++)
                #pragma unroll
                for (int h = 0; h < 8; h++) acc[m][h] = 0ull;

            for (int c = 0; c < NCH; c++) {
                #pragma unroll
                for (int g = 0; g < 4; g++)
                    *(float4*)(xs + (g * 64 + crow) * XSTR + ccol) = r[g];
                __syncthreads();

                if (c + 1 < NCH) { LOADC(c + 1); }   // overlap LDG w/ compute

                const float* qc = qs + (size_t)headg * 8 * NC + c * KC;
                #pragma unroll
                for (int j = 0; j < 4; j++) {
                    ulonglong2 xv[2];
                    #pragma unroll
                    for (int m = 0; m < 2; m++)
                        xv[m] = *(const ulonglong2*)(xs + (rowg + 128 * m) * XSTR + 4 * j);
                    #pragma unroll
                    for (int h = 0; h < 8; h++) {
                        ulonglong2 qv = *(const ulonglong2*)(qc + h * NC + 4 * j);
                        #pragma unroll
                        for (int m = 0; m < 2; m++) {
                            ffma2(acc[m][h], xv[m].x, qv.x);
                            ffma2(acc[m][h], xv[m].y, qv.y);
                        }
                    }
                }
                __syncthreads();
            }
#undef LOADC

            float zacc[8];
            #pragma unroll
            for (int h = 0; h < 8; h++) zacc[h] = 0.0f;
            #pragma unroll
            for (int m = 0; m < 2; m++) {
                int rr = tile * TILE_R + rowg + 128 * m;
                float s[8];
                #pragma unroll
                for (int h = 0; h < 8; h++) {
                    s[h] = (lo2(acc[m][h]) + hi2(acc[m][h])) * SCALE;
                    zacc[h] += expf(s[h]);
                }
                float* dst = g_scores + ((size_t)b * NT + rr) * NH + headg * 8;
                *(float4*)(dst + 0) = make_float4(s[0], s[1], s[2], s[3]);
                *(float4*)(dst + 4) = make_float4(s[4], s[5], s[6], s[7]);
            }
            #pragma unroll
            for (int h = 0; h < 8; h++) {
                float v = zacc[h];
                #pragma unroll
                for (int m2 = 16; m2 >= 1; m2 >>= 1)
                    v += __shfl_xor_sync(0xffffffffu, v, m2);
                if ((tid & 31) == 0) atomicAdd(&zsh[headg * 8 + h], v);
            }
            __syncthreads();
            if (tid < NH) atomicAdd(&g_Z[b * NH + tid], zsh[tid]);
            // publish: all STG/atomics visible before done-increment
            __threadfence();
            __syncthreads();
            if (tid == 0) atomicAdd(&g_done[b], 1u);

        } else {
            // ================= POOL tile: 128 rows =================
            const int b = grp * 8 + local / PL_TILES;
            const int tile = local % PL_TILES;

            if (tid == 0) {
                while (atomicAdd(&g_done[b], 0u) < (unsigned)SC_TILES)
                    __nanosleep(200);
            }
            __syncthreads();
            __threadfence();

            if (tid < 16) rz[tid] = 1.0f / __ldcg(&g_Z[b * NH + tid]);
            __syncthreads();

            if (tid < 128) {
                const int rr = tile * 128 + tid;
                const float4* sp = (const float4*)(g_scores + ((size_t)b * NT + rr) * NH);
                float4 s0 = sp[0], s1 = sp[1], s2 = sp[2], s3 = sp[3];
                float w = expf(s0.x) * rz[0]  + expf(s0.y) * rz[1]
                        + expf(s0.z) * rz[2]  + expf(s0.w) * rz[3]
                        + expf(s1.x) * rz[4]  + expf(s1.y) * rz[5]
                        + expf(s1.z) * rz[6]  + expf(s1.w) * rz[7]
                        + expf(s2.x) * rz[8]  + expf(s2.y) * rz[9]
                        + expf(s2.z) * rz[10] + expf(s2.w) * rz[11]
                        + expf(s3.x) * rz[12] + expf(s3.y) * rz[13]
                        + expf(s3.z) * rz[14] + expf(s3.w) * rz[15];
                ws[tid] = w * (1.0f / 16.0f);
            }
            __syncthreads();

            const int c = tid * 4;
            float4 acc4 = make_float4(0.f, 0.f, 0.f, 0.f);
            const float* xb = x + ((size_t)b * NT + tile * 128) * NC + c;
            #pragma unroll 8
            for (int rr = 0; rr < 128; rr++) {
                float4 xv = *(const float4*)(xb + (size_t)rr * NC);
                float w = ws[rr];
                acc4.x += w * xv.x; acc4.y += w * xv.y;
                acc4.z += w * xv.z; acc4.w += w * xv.w;
            }
            float* pp = g_pooled + b * NC + c;
            atomicAdd(pp + 0, acc4.x);
            atomicAdd(pp + 1, acc4.y);
            atomicAdd(pp + 2, acc4.z);
            atomicAdd(pp + 3, acc4.w);
        }
    }
}

// ============================================================
// K3: out[b,j] = <pooled[b,:], W[j,:]> + bias[j]
// ============================================================
__global__ void __launch_bounds__(256)
k_proj(const float* __restrict__ w, const float* __restrict__ bias,
       float* __restrict__ out) {
    const int warp = threadIdx.x >> 5, lane = threadIdx.x & 31;
    const int j = blockIdx.x * 8 + warp;

    float4 wr[8];
    const float4* wp = (const float4*)(w + (size_t)j * NC);
    #pragma unroll
    for (int i = 0; i < 8; i++) wr[i] = wp[lane + 32 * i];
    const float bj = bias[j];

    const int b0 = blockIdx.y * 8;
    for (int b = b0; b < b0 + 8; b++) {
        const float4* pp = (const float4*)(g_pooled + b * NC);
        float acc = 0.0f;
        #pragma unroll
        for (int i = 0; i < 8; i++) {
            float4 pv = pp[lane + 32 * i];
            acc += pv.x * wr[i].x + pv.y * wr[i].y
                 + pv.z * wr[i].z + pv.w * wr[i].w;
        }
        #pragma unroll
        for (int m = 16; m >= 1; m >>= 1)
            acc += __shfl_xor_sync(0xffffffffu, acc, m);
        if (lane == 0) out[b * NC + j] = acc + bj;
    }
}

// ============================================================
extern "C" void kernel_launch(void* const* d_in, const int* in_sizes, int n_in,
                              void* d_out, int out_size) {
    const float* x  = (const float*)d_in[0];
    const float* q  = (const float*)d_in[1];
    const float* pw = (const float*)d_in[2];
    const float* pb = (const float*)d_in[3];
    float* out      = (float*)d_out;

    const int smem = (NH * NC + TILE_R * XSTR) * (int)sizeof(float);  // 84 KB
    cudaFuncSetAttribute(k_main, cudaFuncAttributeMaxDynamicSharedMemorySize, smem);

    k_zero<<<128, 256>>>();
    k_main<<<296, 256, smem>>>(x, q);
    k_proj<<<dim3(128, 4), 256>>>(pw, pb, out);
}